// round 12
// baseline (speedup 1.0000x reference)
#include <cuda_runtime.h>
#include <cuda_bf16.h>
#include <cstdint>

#define NODE 112

// Pre-split weight planes, concatenated [N][K] row-major:
//   W1 [256][112] @ 0, W2 [256][256], W3 [128][256], W4 [64][128].
#define W1_OFF 0
#define W2_OFF 28672
#define W3_OFF 94208
#define W4_OFF 126976
#define W_TOTAL 135168
__device__ __nv_bfloat16 w_hi[W_TOTAL];
__device__ __nv_bfloat16 w_lo[W_TOTAL];

// Per-graph projected activations g' (transposed [n][m], split planes).
__device__ __nv_bfloat16 gT_hi[(size_t)4096 * 256 * NODE];
__device__ __nv_bfloat16 gT_lo[(size_t)4096 * 256 * NODE];

// SMEM layout (byte offsets):
//   xs planes [112][120] bf16 x2   53,760
//   hs planes [112][264] bf16 x2  118,272
//   bst: 3 bufs x 2 planes x [64][72] bf16 = 55,296  (row stride 144 B)
//   g5 (112 f32) + red (128 f32)
#define XS_HI_OFF   0
#define XS_LO_OFF   26880
#define HS_HI_OFF   53760
#define HS_LO_OFF   112896
#define BST_OFF     172032
#define BST_BUF     18432
#define BST_PLANE   9216
#define G5_OFF      227328
#define RED_OFF     227776
#define SMEM_BYTES  228352

#define XS_PITCH 120
#define HS_PITCH 264
#define BST_ROWB 144

// Named-barrier producer/consumer ring: ids 1..3 = full[s], 4..6 = empty[s].
// 448 consumer threads + 64 producer threads = 512 total arrivals each.
#define BAR_SYNC(id)   asm volatile("bar.sync %0, 512;"   :: "r"(id) : "memory")
#define BAR_ARRIVE(id) asm volatile("bar.arrive %0, 512;" :: "r"(id) : "memory")

__device__ __forceinline__ void split_bf16(float v, __nv_bfloat16& hi, __nv_bfloat16& lo) {
    hi = __float2bfloat16_rn(v);
    lo = __float2bfloat16_rn(v - __bfloat162float(hi));
}

__device__ __forceinline__ void mma_bf16(float (&c)[4],
                                         uint32_t a0, uint32_t a1, uint32_t a2, uint32_t a3,
                                         uint32_t b0, uint32_t b1) {
    asm volatile("mma.sync.aligned.m16n8k16.row.col.f32.bf16.bf16.f32 "
                 "{%0,%1,%2,%3}, {%4,%5,%6,%7}, {%8,%9}, {%0,%1,%2,%3};\n"
                 : "+f"(c[0]), "+f"(c[1]), "+f"(c[2]), "+f"(c[3])
                 : "r"(a0), "r"(a1), "r"(a2), "r"(a3), "r"(b0), "r"(b1));
}
__device__ __forceinline__ void ldmat4(uint32_t& r0, uint32_t& r1, uint32_t& r2, uint32_t& r3,
                                       uint32_t addr) {
    asm volatile("ldmatrix.sync.aligned.m8n8.x4.shared.b16 {%0,%1,%2,%3}, [%4];"
                 : "=r"(r0), "=r"(r1), "=r"(r2), "=r"(r3) : "r"(addr));
}
__device__ __forceinline__ void cp16(uint32_t dst, const void* src) {
    asm volatile("cp.async.ca.shared.global [%0], [%1], 16;" :: "r"(dst), "l"(src));
}
__device__ __forceinline__ void cp_commit() { asm volatile("cp.async.commit_group;"); }
template<int N> __device__ __forceinline__ void cp_wait() {
    asm volatile("cp.async.wait_group %0;" :: "n"(N));
}

// Producer-side staging: one B tile ([64 n][Kc k], both planes), 64 threads.
template<int SRC_PITCH, int Kc>
__device__ __forceinline__ void load_tile_p(uint32_t dst_base,
                                            const __nv_bfloat16* __restrict__ Bhi,
                                            const __nv_bfloat16* __restrict__ Blo,
                                            int n0, int k0, int ptid) {
    constexpr int CH  = Kc / 8;       // 16B chunks per row (8 or 6)
    constexpr int TOT = 64 * CH;
    #pragma unroll
    for (int i = ptid; i < 2 * TOT; i += 64) {
        int p  = (i >= TOT);
        int ii = p ? i - TOT : i;
        int rr = ii / CH;
        int cc = ii - rr * CH;
        const __nv_bfloat16* src =
            (p ? Blo : Bhi) + (size_t)(n0 + rr) * SRC_PITCH + k0 + cc * 8;
        cp16(dst_base + p * BST_PLANE + rr * BST_ROWB + cc * 16, src);
    }
}

// Frag set for one k16 step (R10 mapping, unchanged).
__device__ __forceinline__ void load_frags(uint32_t aH, uint32_t aL,
                                           uint32_t bH, uint32_t bL, int kk,
                                           uint32_t (&fa)[8], uint32_t (&fb)[16]) {
    const uint32_t ko = (uint32_t)(kk << 1);
    ldmat4(fb[0],  fb[1],  fb[2],  fb[3],  bH + ko);
    ldmat4(fb[4],  fb[5],  fb[6],  fb[7],  bL + ko);
    ldmat4(fb[8],  fb[9],  fb[10], fb[11], bH + 16 * BST_ROWB + ko);
    ldmat4(fb[12], fb[13], fb[14], fb[15], bL + 16 * BST_ROWB + ko);
    ldmat4(fa[0], fa[1], fa[2], fa[3], aH + ko);
    ldmat4(fa[4], fa[5], fa[6], fa[7], aL + ko);
}

__device__ __forceinline__ void mma_step(float (&c)[4][4],
                                         const uint32_t (&fa)[8], const uint32_t (&fb)[16]) {
    #pragma unroll
    for (int jp = 0; jp < 2; jp++) {
        const int o = jp * 8;
        mma_bf16(c[2 * jp],     fa[0], fa[1], fa[2], fa[3], fb[o + 0], fb[o + 1]); // hi*hi
        mma_bf16(c[2 * jp],     fa[0], fa[1], fa[2], fa[3], fb[o + 4], fb[o + 5]); // hi*lo
        mma_bf16(c[2 * jp],     fa[4], fa[5], fa[6], fa[7], fb[o + 0], fb[o + 1]); // lo*hi
        mma_bf16(c[2 * jp + 1], fa[0], fa[1], fa[2], fa[3], fb[o + 2], fb[o + 3]);
        mma_bf16(c[2 * jp + 1], fa[0], fa[1], fa[2], fa[3], fb[o + 6], fb[o + 7]);
        mma_bf16(c[2 * jp + 1], fa[4], fa[5], fa[6], fa[7], fb[o + 2], fb[o + 3]);
    }
}

template<int Kc>
__device__ __forceinline__ void compute_tile(uint32_t aH, uint32_t aL,
                                             uint32_t bH, uint32_t bL,
                                             float (&c)[4][4]) {
    uint32_t fa[2][8], fb[2][16];
    load_frags(aH, aL, bH, bL, 0, fa[0], fb[0]);
    #pragma unroll
    for (int i = 0; i < Kc / 16; i++) {
        const int cur = i & 1;
        if ((i + 1) * 16 < Kc)
            load_frags(aH, aL, bH, bL, (i + 1) * 16, fa[cur ^ 1], fb[cur ^ 1]);
        mma_step(c, fa[cur], fb[cur]);
    }
}

// C[112][NT] = A[112][KT] @ B^T; B as split planes [NT][SRC_PITCH] (global).
// Warp-specialized: warps 0-13 consume (MMA), warps 14-15 produce (cp.async).
// Handoff via named-barrier ring; `gt` is the CTA-global tile counter that
// keeps ring stage/arrival counts continuous across GEMMs.
template<int KT, int NT, bool TO_SMEM, int PITCH_A, int SRC_PITCH>
__device__ __forceinline__ void gemm(const __nv_bfloat16* __restrict__ Ahi,
                                     const __nv_bfloat16* __restrict__ Alo,
                                     const __nv_bfloat16* __restrict__ Bhi,
                                     const __nv_bfloat16* __restrict__ Blo,
                                     const float* __restrict__ bias,
                                     __nv_bfloat16* hhi, __nv_bfloat16* hlo,
                                     __nv_bfloat16* gThi, __nv_bfloat16* gTlo,
                                     uint32_t bst_base, const int tid, int& gt) {
    constexpr int NC    = NT / 64;
    constexpr int KC    = (KT + 63) / 64;
    constexpr int KLAST = KT - 64 * (KC - 1);   // 64 or 48
    constexpr int T     = NC * KC;

    const int warp = tid >> 5, lane = tid & 31;

    if (warp >= 14) {
        // ---- producers (64 threads) ----
        const int ptid = tid - 448;
        #pragma unroll 1
        for (int t = 0; t < T; t++) {
            const int nc = t / KC, kc = t - nc * KC;
            const int s = (gt + t) % 3;
            if (gt + t >= 3) BAR_SYNC(4 + s);           // buffer s free (consumers done t-3)
            const uint32_t dst = bst_base + (uint32_t)s * BST_BUF;
            if (kc == KC - 1 && KLAST != 64)
                load_tile_p<SRC_PITCH, KLAST>(dst, Bhi, Blo, nc * 64, kc * 64, ptid);
            else
                load_tile_p<SRC_PITCH, 64>(dst, Bhi, Blo, nc * 64, kc * 64, ptid);
            cp_commit();
            if (t >= 2) { cp_wait<2>(); BAR_ARRIVE(1 + (gt + t - 2) % 3); }  // tile t-2 ready
        }
        if (T >= 2) { cp_wait<1>(); BAR_ARRIVE(1 + (gt + T - 2) % 3); }
        cp_wait<0>(); BAR_ARRIVE(1 + (gt + T - 1) % 3);
    } else {
        // ---- consumers (448 threads, 14 x m16n32 tiles) ----
        const int g = lane >> 2, t4 = lane & 3;
        const int q = lane >> 3, r8 = lane & 7;
        const int rb = warp >> 1, half = warp & 1;
        const int m0 = rb * 16;

        const uint32_t arow = (m0 + r8 + ((q & 1) << 3)) * PITCH_A + ((q >> 1) << 3);
        const uint32_t aHiB = (uint32_t)__cvta_generic_to_shared(Ahi) + (arow << 1);
        const uint32_t aLoB = (uint32_t)__cvta_generic_to_shared(Alo) + (arow << 1);
        const uint32_t bRow = ((half << 5) + ((q >> 1) << 3) + r8) * BST_ROWB
                            + (((q & 1) << 3) << 1);

        float c[4][4];
        #pragma unroll 1
        for (int t = 0; t < T; t++) {
            const int nc = t / KC, kc = t - nc * KC;
            const int s = (gt + t) % 3;
            BAR_SYNC(1 + s);                            // tile t staged

            if (kc == 0) {
                #pragma unroll
                for (int j = 0; j < 4; j++) { c[j][0]=0.f; c[j][1]=0.f; c[j][2]=0.f; c[j][3]=0.f; }
            }
            const uint32_t bH = bst_base + (uint32_t)s * BST_BUF + bRow;
            const uint32_t bL = bH + BST_PLANE;
            const uint32_t aH = aHiB + (uint32_t)((kc * 64) << 1);
            const uint32_t aL = aLoB + (uint32_t)((kc * 64) << 1);
            if (kc == KC - 1 && KLAST != 64)
                compute_tile<KLAST>(aH, aL, bH, bL, c);
            else
                compute_tile<64>(aH, aL, bH, bL, c);

            if (kc == KC - 1) {
                const int mr = m0 + g;
                #pragma unroll
                for (int j = 0; j < 4; j++) {
                    const int n = nc * 64 + (half << 5) + 8 * j + 2 * t4;
                    if constexpr (TO_SMEM) {
                        const float bv0 = __ldg(&bias[n]);
                        const float bv1 = __ldg(&bias[n + 1]);
                        const float v00 = fmaxf(c[j][0] + bv0, 0.f);
                        const float v01 = fmaxf(c[j][1] + bv1, 0.f);
                        const float v10 = fmaxf(c[j][2] + bv0, 0.f);
                        const float v11 = fmaxf(c[j][3] + bv1, 0.f);
                        split_bf16(v00, hhi[mr * HS_PITCH + n],           hlo[mr * HS_PITCH + n]);
                        split_bf16(v01, hhi[mr * HS_PITCH + n + 1],       hlo[mr * HS_PITCH + n + 1]);
                        split_bf16(v10, hhi[(mr + 8) * HS_PITCH + n],     hlo[(mr + 8) * HS_PITCH + n]);
                        split_bf16(v11, hhi[(mr + 8) * HS_PITCH + n + 1], hlo[(mr + 8) * HS_PITCH + n + 1]);
                    } else {
                        split_bf16(c[j][0], gThi[(size_t)n * NODE + mr],           gTlo[(size_t)n * NODE + mr]);
                        split_bf16(c[j][1], gThi[(size_t)(n + 1) * NODE + mr],     gTlo[(size_t)(n + 1) * NODE + mr]);
                        split_bf16(c[j][2], gThi[(size_t)n * NODE + mr + 8],       gTlo[(size_t)n * NODE + mr + 8]);
                        split_bf16(c[j][3], gThi[(size_t)(n + 1) * NODE + mr + 8], gTlo[(size_t)(n + 1) * NODE + mr + 8]);
                    }
                }
            }
            BAR_ARRIVE(4 + s);                          // buffer s consumed
        }
    }
    gt += T;
}

__global__ void prep_weights(const float* __restrict__ W1, const float* __restrict__ W2,
                             const float* __restrict__ W3, const float* __restrict__ W4) {
    int i = blockIdx.x * 256 + threadIdx.x;
    if (i >= W_TOTAL) return;
    float v;
    if (i < W2_OFF)      v = W1[i];
    else if (i < W3_OFF) v = W2[i - W2_OFF];
    else if (i < W4_OFF) v = W3[i - W3_OFF];
    else                 v = W4[i - W4_OFF];
    split_bf16(v, w_hi[i], w_lo[i]);
}

__global__ void __launch_bounds__(512, 1)
gcn_fused_kernel(const float* __restrict__ x,
                 const float* __restrict__ b1, const float* __restrict__ b2,
                 const float* __restrict__ b3, const float* __restrict__ b4,
                 const float* __restrict__ W5, const float* __restrict__ b5,
                 const float* __restrict__ Wf, const float* __restrict__ bf,
                 float* __restrict__ out) {
    extern __shared__ char sm[];
    __nv_bfloat16* xs_hi = (__nv_bfloat16*)(sm + XS_HI_OFF);
    __nv_bfloat16* xs_lo = (__nv_bfloat16*)(sm + XS_LO_OFF);
    __nv_bfloat16* hs_hi = (__nv_bfloat16*)(sm + HS_HI_OFF);
    __nv_bfloat16* hs_lo = (__nv_bfloat16*)(sm + HS_LO_OFF);
    float* g5  = (float*)(sm + G5_OFF);
    float* red = (float*)(sm + RED_OFF);
    const uint32_t bst_base = (uint32_t)__cvta_generic_to_shared(sm + BST_OFF);

    const int tid = threadIdx.x;
    const int b = blockIdx.x;
    __nv_bfloat16* gThi = gT_hi + (size_t)b * (256 * NODE);
    __nv_bfloat16* gTlo = gT_lo + (size_t)b * (256 * NODE);

    const float* xb = x + (size_t)b * (NODE * NODE);
    for (int idx = tid; idx < NODE * NODE; idx += 512) {
        int m = idx / NODE;
        int j = idx - m * NODE;
        split_bf16(xb[idx], xs_hi[m * XS_PITCH + j], xs_lo[m * XS_PITCH + j]);
    }
    __syncthreads();

    int gt = 0;   // global tile counter — keeps the barrier ring continuous

    // Layer 1: h = relu(x @ W1^T + b1)                          [112,256]
    gemm<112, 256, true , XS_PITCH, 112>(xs_hi, xs_lo, w_hi + W1_OFF, w_lo + W1_OFF, b1,
                                         hs_hi, hs_lo, nullptr, nullptr, bst_base, tid, gt);
    __syncthreads();
    // Layer 2: g' = h @ W2^T ; h = relu(x @ g' + b2)            [112,256]
    gemm<256, 256, false, HS_PITCH, 256>(hs_hi, hs_lo, w_hi + W2_OFF, w_lo + W2_OFF, nullptr,
                                         nullptr, nullptr, gThi, gTlo, bst_base, tid, gt);
    __threadfence_block(); __syncthreads();
    gemm<112, 256, true , XS_PITCH, 112>(xs_hi, xs_lo, gThi, gTlo, b2,
                                         hs_hi, hs_lo, nullptr, nullptr, bst_base, tid, gt);
    __syncthreads();
    // Layer 3                                                   [112,128]
    gemm<256, 128, false, HS_PITCH, 256>(hs_hi, hs_lo, w_hi + W3_OFF, w_lo + W3_OFF, nullptr,
                                         nullptr, nullptr, gThi, gTlo, bst_base, tid, gt);
    __threadfence_block(); __syncthreads();
    gemm<112, 128, true , XS_PITCH, 112>(xs_hi, xs_lo, gThi, gTlo, b3,
                                         hs_hi, hs_lo, nullptr, nullptr, bst_base, tid, gt);
    __syncthreads();
    // Layer 4                                                   [112,64]
    gemm<128, 64,  false, HS_PITCH, 128>(hs_hi, hs_lo, w_hi + W4_OFF, w_lo + W4_OFF, nullptr,
                                         nullptr, nullptr, gThi, gTlo, bst_base, tid, gt);
    __threadfence_block(); __syncthreads();
    gemm<112, 64,  true , XS_PITCH, 112>(xs_hi, xs_lo, gThi, gTlo, b4,
                                         hs_hi, hs_lo, nullptr, nullptr, bst_base, tid, gt);
    __syncthreads();

    // Layer 5 (project-first): g5[m] = sum_k h[m][k] * W5[k]
    if (tid < NODE) {
        float acc = 0.f;
        #pragma unroll
        for (int k = 0; k < 64; k++) {
            float hv = __bfloat162float(hs_hi[tid * HS_PITCH + k])
                     + __bfloat162float(hs_lo[tid * HS_PITCH + k]);
            acc += hv * __ldg(&W5[k]);
        }
        g5[tid] = acc;
    }
    __syncthreads();
    if (tid < NODE) {
        float acc = 0.f;
        #pragma unroll
        for (int j = 0; j < NODE; j++) {
            float xv = __bfloat162float(xs_hi[tid * XS_PITCH + j])
                     + __bfloat162float(xs_lo[tid * XS_PITCH + j]);
            acc += xv * g5[j];
        }
        float h5 = fmaxf(acc + __ldg(&b5[0]), 0.f);
        red[tid] = h5 * __ldg(&Wf[tid]);
    }
    __syncthreads();
    if (tid == 0) {
        float s = 0.f;
        #pragma unroll
        for (int i = 0; i < NODE; i++) s += red[i];
        out[b] = s + __ldg(&bf[0]);
    }
}

extern "C" void kernel_launch(void* const* d_in, const int* in_sizes, int n_in,
                              void* d_out, int out_size) {
    const float* x  = (const float*)d_in[0];
    const float* W1 = (const float*)d_in[1];
    const float* b1 = (const float*)d_in[2];
    const float* W2 = (const float*)d_in[3];
    const float* b2 = (const float*)d_in[4];
    const float* W3 = (const float*)d_in[5];
    const float* b3 = (const float*)d_in[6];
    const float* W4 = (const float*)d_in[7];
    const float* b4 = (const float*)d_in[8];
    const float* W5 = (const float*)d_in[9];
    const float* b5 = (const float*)d_in[10];
    const float* Wf = (const float*)d_in[11];
    const float* bf = (const float*)d_in[12];
    float* out = (float*)d_out;

    prep_weights<<<(W_TOTAL + 255) / 256, 256>>>(W1, W2, W3, W4);

    cudaFuncSetAttribute(gcn_fused_kernel,
                         cudaFuncAttributeMaxDynamicSharedMemorySize, SMEM_BYTES);
    gcn_fused_kernel<<<4096, 512, SMEM_BYTES>>>(
        x, b1, b2, b3, b4, W5, b5, Wf, bf, out);
}

// round 13
// speedup vs baseline: 1.0569x; 1.0569x over previous
#include <cuda_runtime.h>
#include <cuda_bf16.h>
#include <cstdint>

#define NODE 112

// Pre-split weight planes, concatenated [N][K] row-major:
//   W1 [256][112] @ 0, W2 [256][256], W3 [128][256], W4 [64][128].
#define W1_OFF 0
#define W2_OFF 28672
#define W3_OFF 94208
#define W4_OFF 126976
#define W_TOTAL 135168
__device__ __nv_bfloat16 w_hi[W_TOTAL];
__device__ __nv_bfloat16 w_lo[W_TOTAL];

// Per-graph projected activations g' (transposed [n][m], split planes).
__device__ __nv_bfloat16 gT_hi[(size_t)4096 * 256 * NODE];
__device__ __nv_bfloat16 gT_lo[(size_t)4096 * 256 * NODE];

// SMEM layout (byte offsets): identical to R10 (best).
#define XS_HI_OFF   0
#define XS_LO_OFF   26880
#define HS_HI_OFF   53760
#define HS_LO_OFF   112896
#define BST_OFF     172032
#define BST_BUF     18432
#define BST_PLANE   9216
#define G5_OFF      227328
#define RED_OFF     227776
#define SMEM_BYTES  228352

#define XS_PITCH 120
#define HS_PITCH 264
#define BST_ROWB 144

__device__ __forceinline__ void split_bf16(float v, __nv_bfloat16& hi, __nv_bfloat16& lo) {
    hi = __float2bfloat16_rn(v);
    lo = __float2bfloat16_rn(v - __bfloat162float(hi));
}

__device__ __forceinline__ void mma_bf16(float (&c)[4],
                                         uint32_t a0, uint32_t a1, uint32_t a2, uint32_t a3,
                                         uint32_t b0, uint32_t b1) {
    asm volatile("mma.sync.aligned.m16n8k16.row.col.f32.bf16.bf16.f32 "
                 "{%0,%1,%2,%3}, {%4,%5,%6,%7}, {%8,%9}, {%0,%1,%2,%3};\n"
                 : "+f"(c[0]), "+f"(c[1]), "+f"(c[2]), "+f"(c[3])
                 : "r"(a0), "r"(a1), "r"(a2), "r"(a3), "r"(b0), "r"(b1));
}
__device__ __forceinline__ void ldmat4(uint32_t& r0, uint32_t& r1, uint32_t& r2, uint32_t& r3,
                                       uint32_t addr) {
    asm volatile("ldmatrix.sync.aligned.m8n8.x4.shared.b16 {%0,%1,%2,%3}, [%4];"
                 : "=r"(r0), "=r"(r1), "=r"(r2), "=r"(r3) : "r"(addr));
}
__device__ __forceinline__ void cp16(uint32_t dst, const void* src) {
    asm volatile("cp.async.ca.shared.global [%0], [%1], 16;" :: "r"(dst), "l"(src));
}
__device__ __forceinline__ void cp_commit() { asm volatile("cp.async.commit_group;"); }
template<int N> __device__ __forceinline__ void cp_wait() {
    asm volatile("cp.async.wait_group %0;" :: "n"(N));
}

// Stage one B tile ([64 n][Kc k], both planes) — all 512 threads (R10).
template<int SRC_PITCH, int Kc>
__device__ __forceinline__ void load_tile(uint32_t dst_base,
                                          const __nv_bfloat16* __restrict__ Bhi,
                                          const __nv_bfloat16* __restrict__ Blo,
                                          int n0, int k0, int tid) {
    constexpr int CH  = Kc / 8;
    constexpr int TOT = 64 * CH;
    #pragma unroll
    for (int base = 0; base < 2 * TOT; base += 512) {
        int i = base + tid;
        if (i < 2 * TOT) {
            int p  = (i >= TOT);
            int ii = p ? i - TOT : i;
            int rr = ii / CH;
            int cc = ii - rr * CH;
            const __nv_bfloat16* src =
                (p ? Blo : Bhi) + (size_t)(n0 + rr) * SRC_PITCH + k0 + cc * 8;
            cp16(dst_base + p * BST_PLANE + rr * BST_ROWB + cc * 16, src);
        }
    }
}

// ---- B fragments (shared by both tile shapes): n32, hi+lo, per k16 ----------
__device__ __forceinline__ void load_fragsB(uint32_t bH, uint32_t bL, int kk,
                                            uint32_t (&fb)[16]) {
    const uint32_t ko = (uint32_t)(kk << 1);
    ldmat4(fb[0],  fb[1],  fb[2],  fb[3],  bH + ko);
    ldmat4(fb[4],  fb[5],  fb[6],  fb[7],  bL + ko);
    ldmat4(fb[8],  fb[9],  fb[10], fb[11], bH + 16 * BST_ROWB + ko);
    ldmat4(fb[12], fb[13], fb[14], fb[15], bL + 16 * BST_ROWB + ko);
}

// ---- m16n32 path (R10, warps 6-7) -------------------------------------------
__device__ __forceinline__ void load_fragsA16(uint32_t aH, uint32_t aL, int kk,
                                              uint32_t (&fa)[8]) {
    const uint32_t ko = (uint32_t)(kk << 1);
    ldmat4(fa[0], fa[1], fa[2], fa[3], aH + ko);
    ldmat4(fa[4], fa[5], fa[6], fa[7], aL + ko);
}
__device__ __forceinline__ void mma_step16(float (&c)[4][4],
                                           const uint32_t (&fa)[8], const uint32_t (&fb)[16]) {
    #pragma unroll
    for (int jp = 0; jp < 2; jp++) {
        const int o = jp * 8;
        mma_bf16(c[2 * jp],     fa[0], fa[1], fa[2], fa[3], fb[o + 0], fb[o + 1]);
        mma_bf16(c[2 * jp],     fa[0], fa[1], fa[2], fa[3], fb[o + 4], fb[o + 5]);
        mma_bf16(c[2 * jp],     fa[4], fa[5], fa[6], fa[7], fb[o + 0], fb[o + 1]);
        mma_bf16(c[2 * jp + 1], fa[0], fa[1], fa[2], fa[3], fb[o + 2], fb[o + 3]);
        mma_bf16(c[2 * jp + 1], fa[0], fa[1], fa[2], fa[3], fb[o + 6], fb[o + 7]);
        mma_bf16(c[2 * jp + 1], fa[4], fa[5], fa[6], fa[7], fb[o + 2], fb[o + 3]);
    }
}
template<int Kc>
__device__ __forceinline__ void compute_tile16(uint32_t aH, uint32_t aL,
                                               uint32_t bH, uint32_t bL,
                                               float (&c)[4][4]) {
    uint32_t fa[2][8], fb[2][16];
    load_fragsB(bH, bL, 0, fb[0]);
    load_fragsA16(aH, aL, 0, fa[0]);
    #pragma unroll
    for (int i = 0; i < Kc / 16; i++) {
        const int cur = i & 1;
        if ((i + 1) * 16 < Kc) {
            load_fragsB(bH, bL, (i + 1) * 16, fb[cur ^ 1]);
            load_fragsA16(aH, aL, (i + 1) * 16, fa[cur ^ 1]);
        }
        mma_step16(c, fa[cur], fb[cur]);
    }
}

// ---- m32n32 path (warps 0-5): 8 ldmat4 per 24 HMMA --------------------------
// fa: [0..3] hi mi0, [4..7] hi mi1, [8..11] lo mi0, [12..15] lo mi1
template<int A16B>   // byte offset between the two m16 row-blocks (= 32*PITCH_A)
__device__ __forceinline__ void load_fragsA32(uint32_t aH, uint32_t aL, int kk,
                                              uint32_t (&fa)[16]) {
    const uint32_t ko = (uint32_t)(kk << 1);
    ldmat4(fa[0],  fa[1],  fa[2],  fa[3],  aH + ko);
    ldmat4(fa[4],  fa[5],  fa[6],  fa[7],  aH + A16B + ko);
    ldmat4(fa[8],  fa[9],  fa[10], fa[11], aL + ko);
    ldmat4(fa[12], fa[13], fa[14], fa[15], aL + A16B + ko);
}
__device__ __forceinline__ void mma_step32(float (&c)[2][4][4],
                                           const uint32_t (&fa)[16], const uint32_t (&fb)[16]) {
    #pragma unroll
    for (int mi = 0; mi < 2; mi++) {
        const int ah = mi * 4, al = 8 + mi * 4;
        #pragma unroll
        for (int jp = 0; jp < 2; jp++) {
            const int o = jp * 8;
            mma_bf16(c[mi][2 * jp],     fa[ah], fa[ah+1], fa[ah+2], fa[ah+3], fb[o + 0], fb[o + 1]);
            mma_bf16(c[mi][2 * jp],     fa[ah], fa[ah+1], fa[ah+2], fa[ah+3], fb[o + 4], fb[o + 5]);
            mma_bf16(c[mi][2 * jp],     fa[al], fa[al+1], fa[al+2], fa[al+3], fb[o + 0], fb[o + 1]);
            mma_bf16(c[mi][2 * jp + 1], fa[ah], fa[ah+1], fa[ah+2], fa[ah+3], fb[o + 2], fb[o + 3]);
            mma_bf16(c[mi][2 * jp + 1], fa[ah], fa[ah+1], fa[ah+2], fa[ah+3], fb[o + 6], fb[o + 7]);
            mma_bf16(c[mi][2 * jp + 1], fa[al], fa[al+1], fa[al+2], fa[al+3], fb[o + 2], fb[o + 3]);
        }
    }
}
template<int Kc, int A16B>
__device__ __forceinline__ void compute_tile32(uint32_t aH, uint32_t aL,
                                               uint32_t bH, uint32_t bL,
                                               float (&c)[2][4][4]) {
    uint32_t fa[2][16], fb[2][16];
    load_fragsB(bH, bL, 0, fb[0]);
    load_fragsA32<A16B>(aH, aL, 0, fa[0]);
    #pragma unroll
    for (int i = 0; i < Kc / 16; i++) {
        const int cur = i & 1;
        if ((i + 1) * 16 < Kc) {
            load_fragsB(bH, bL, (i + 1) * 16, fb[cur ^ 1]);
            load_fragsA32<A16B>(aH, aL, (i + 1) * 16, fa[cur ^ 1]);
        }
        mma_step32(c, fa[cur], fb[cur]);
    }
}

// Epilogue for one m16-row-block's worth of accumulators (4 n8 frags).
template<bool TO_SMEM>
__device__ __forceinline__ void epilogue_row(float (&c)[4][4], int mr, int nbase,
                                             const float* __restrict__ bias,
                                             __nv_bfloat16* hhi, __nv_bfloat16* hlo,
                                             __nv_bfloat16* gThi, __nv_bfloat16* gTlo,
                                             int t4) {
    #pragma unroll
    for (int j = 0; j < 4; j++) {
        const int n = nbase + 8 * j + 2 * t4;
        if constexpr (TO_SMEM) {
            const float bv0 = __ldg(&bias[n]);
            const float bv1 = __ldg(&bias[n + 1]);
            const float v00 = fmaxf(c[j][0] + bv0, 0.f);
            const float v01 = fmaxf(c[j][1] + bv1, 0.f);
            const float v10 = fmaxf(c[j][2] + bv0, 0.f);
            const float v11 = fmaxf(c[j][3] + bv1, 0.f);
            split_bf16(v00, hhi[mr * HS_PITCH + n],           hlo[mr * HS_PITCH + n]);
            split_bf16(v01, hhi[mr * HS_PITCH + n + 1],       hlo[mr * HS_PITCH + n + 1]);
            split_bf16(v10, hhi[(mr + 8) * HS_PITCH + n],     hlo[(mr + 8) * HS_PITCH + n]);
            split_bf16(v11, hhi[(mr + 8) * HS_PITCH + n + 1], hlo[(mr + 8) * HS_PITCH + n + 1]);
        } else {
            split_bf16(c[j][0], gThi[(size_t)n * NODE + mr],           gTlo[(size_t)n * NODE + mr]);
            split_bf16(c[j][1], gThi[(size_t)(n + 1) * NODE + mr],     gTlo[(size_t)(n + 1) * NODE + mr]);
            split_bf16(c[j][2], gThi[(size_t)n * NODE + mr + 8],       gTlo[(size_t)n * NODE + mr + 8]);
            split_bf16(c[j][3], gThi[(size_t)(n + 1) * NODE + mr + 8], gTlo[(size_t)(n + 1) * NODE + mr + 8]);
        }
    }
}

// C[112][NT] = A[112][KT] @ B^T. R10 orchestration (triple-buffer, one barrier
// per tile, all warps stage); compute warps: 0-5 m32n32 (rows 0-95),
// 6-7 m16n32 (rows 96-111), 8-15 stage-only.
template<int KT, int NT, bool TO_SMEM, int PITCH_A, int SRC_PITCH>
__device__ __forceinline__ void gemm(const __nv_bfloat16* __restrict__ Ahi,
                                     const __nv_bfloat16* __restrict__ Alo,
                                     const __nv_bfloat16* __restrict__ Bhi,
                                     const __nv_bfloat16* __restrict__ Blo,
                                     const float* __restrict__ bias,
                                     __nv_bfloat16* hhi, __nv_bfloat16* hlo,
                                     __nv_bfloat16* gThi, __nv_bfloat16* gTlo,
                                     uint32_t bst_base, const int tid) {
    constexpr int NC    = NT / 64;
    constexpr int KC    = (KT + 63) / 64;
    constexpr int KLAST = KT - 64 * (KC - 1);   // 64 or 48
    constexpr int T     = NC * KC;
    constexpr int A16B  = 32 * PITCH_A;         // 16 rows * PITCH_A elems * 2 B

    const int warp = tid >> 5, lane = tid & 31;
    const int g = lane >> 2, t4 = lane & 3;
    const int q = lane >> 3, r8 = lane & 7;
    const bool is32 = warp < 6;
    const bool cw   = warp < 8;
    const int m0   = is32 ? (warp >> 1) * 32 : 96;
    const int half = is32 ? (warp & 1) : (warp - 6);

    const uint32_t arow = (m0 + r8 + ((q & 1) << 3)) * PITCH_A + ((q >> 1) << 3);
    const uint32_t aHiB = (uint32_t)__cvta_generic_to_shared(Ahi) + (arow << 1);
    const uint32_t aLoB = (uint32_t)__cvta_generic_to_shared(Alo) + (arow << 1);
    const uint32_t bRow = ((half << 5) + ((q >> 1) << 3) + r8) * BST_ROWB
                        + (((q & 1) << 3) << 1);

    __syncthreads();   // prior epilogue writes visible before staging/A reads

    load_tile<SRC_PITCH, (KC == 1 && KLAST != 64) ? KLAST : 64>(
        bst_base, Bhi, Blo, 0, 0, tid);
    cp_commit();

    float c32[2][4][4];
    #pragma unroll 1
    for (int t = 0; t < T; t++) {
        const int nc = t / KC, kc = t - nc * KC;
        if (t + 1 < T) {
            const int t1 = t + 1, nc1 = t1 / KC, kc1 = t1 - nc1 * KC;
            const uint32_t wbuf = bst_base + (uint32_t)((t + 1) % 3) * BST_BUF;
            if (kc1 == KC - 1 && KLAST != 64)
                load_tile<SRC_PITCH, KLAST>(wbuf, Bhi, Blo, nc1 * 64, kc1 * 64, tid);
            else
                load_tile<SRC_PITCH, 64>(wbuf, Bhi, Blo, nc1 * 64, kc1 * 64, tid);
            cp_commit();
            cp_wait<1>();
        } else {
            cp_wait<0>();
        }
        __syncthreads();   // tile t visible; buffer (t+1)%3's old readers retired

        if (cw) {
            if (kc == 0) {
                #pragma unroll
                for (int mi = 0; mi < 2; mi++)
                    #pragma unroll
                    for (int j = 0; j < 4; j++) {
                        c32[mi][j][0]=0.f; c32[mi][j][1]=0.f; c32[mi][j][2]=0.f; c32[mi][j][3]=0.f;
                    }
            }
            const uint32_t bH = bst_base + (uint32_t)(t % 3) * BST_BUF + bRow;
            const uint32_t bL = bH + BST_PLANE;
            const uint32_t aH = aHiB + (uint32_t)((kc * 64) << 1);
            const uint32_t aL = aLoB + (uint32_t)((kc * 64) << 1);

            if (is32) {
                if (kc == KC - 1 && KLAST != 64)
                    compute_tile32<KLAST, A16B>(aH, aL, bH, bL, c32);
                else
                    compute_tile32<64, A16B>(aH, aL, bH, bL, c32);
            } else {
                // m16 path uses only c32[0]
                if (kc == KC - 1 && KLAST != 64)
                    compute_tile16<KLAST>(aH, aL, bH, bL, c32[0]);
                else
                    compute_tile16<64>(aH, aL, bH, bL, c32[0]);
            }

            if (kc == KC - 1) {
                const int nbase = nc * 64 + (half << 5);
                epilogue_row<TO_SMEM>(c32[0], m0 + g, nbase, bias, hhi, hlo, gThi, gTlo, t4);
                if (is32)
                    epilogue_row<TO_SMEM>(c32[1], m0 + 16 + g, nbase, bias, hhi, hlo, gThi, gTlo, t4);
            }
        }
    }
}

__global__ void prep_weights(const float* __restrict__ W1, const float* __restrict__ W2,
                             const float* __restrict__ W3, const float* __restrict__ W4) {
    int i = blockIdx.x * 256 + threadIdx.x;
    if (i >= W_TOTAL) return;
    float v;
    if (i < W2_OFF)      v = W1[i];
    else if (i < W3_OFF) v = W2[i - W2_OFF];
    else if (i < W4_OFF) v = W3[i - W3_OFF];
    else                 v = W4[i - W4_OFF];
    split_bf16(v, w_hi[i], w_lo[i]);
}

__global__ void __launch_bounds__(512, 1)
gcn_fused_kernel(const float* __restrict__ x,
                 const float* __restrict__ b1, const float* __restrict__ b2,
                 const float* __restrict__ b3, const float* __restrict__ b4,
                 const float* __restrict__ W5, const float* __restrict__ b5,
                 const float* __restrict__ Wf, const float* __restrict__ bf,
                 float* __restrict__ out) {
    extern __shared__ char sm[];
    __nv_bfloat16* xs_hi = (__nv_bfloat16*)(sm + XS_HI_OFF);
    __nv_bfloat16* xs_lo = (__nv_bfloat16*)(sm + XS_LO_OFF);
    __nv_bfloat16* hs_hi = (__nv_bfloat16*)(sm + HS_HI_OFF);
    __nv_bfloat16* hs_lo = (__nv_bfloat16*)(sm + HS_LO_OFF);
    float* g5  = (float*)(sm + G5_OFF);
    float* red = (float*)(sm + RED_OFF);
    const uint32_t bst_base = (uint32_t)__cvta_generic_to_shared(sm + BST_OFF);

    const int tid = threadIdx.x;
    const int b = blockIdx.x;
    __nv_bfloat16* gThi = gT_hi + (size_t)b * (256 * NODE);
    __nv_bfloat16* gTlo = gT_lo + (size_t)b * (256 * NODE);

    const float* xb = x + (size_t)b * (NODE * NODE);
    for (int idx = tid; idx < NODE * NODE; idx += 512) {
        int m = idx / NODE;
        int j = idx - m * NODE;
        split_bf16(xb[idx], xs_hi[m * XS_PITCH + j], xs_lo[m * XS_PITCH + j]);
    }

    // Layer 1: h = relu(x @ W1^T + b1)                          [112,256]
    gemm<112, 256, true , XS_PITCH, 112>(xs_hi, xs_lo, w_hi + W1_OFF, w_lo + W1_OFF, b1,
                                         hs_hi, hs_lo, nullptr, nullptr, bst_base, tid);
    // Layer 2: g' = h @ W2^T ; h = relu(x @ g' + b2)            [112,256]
    gemm<256, 256, false, HS_PITCH, 256>(hs_hi, hs_lo, w_hi + W2_OFF, w_lo + W2_OFF, nullptr,
                                         nullptr, nullptr, gThi, gTlo, bst_base, tid);
    gemm<112, 256, true , XS_PITCH, 112>(xs_hi, xs_lo, gThi, gTlo, b2,
                                         hs_hi, hs_lo, nullptr, nullptr, bst_base, tid);
    // Layer 3                                                   [112,128]
    gemm<256, 128, false, HS_PITCH, 256>(hs_hi, hs_lo, w_hi + W3_OFF, w_lo + W3_OFF, nullptr,
                                         nullptr, nullptr, gThi, gTlo, bst_base, tid);
    gemm<112, 128, true , XS_PITCH, 112>(xs_hi, xs_lo, gThi, gTlo, b3,
                                         hs_hi, hs_lo, nullptr, nullptr, bst_base, tid);
    // Layer 4                                                   [112,64]
    gemm<128, 64,  false, HS_PITCH, 128>(hs_hi, hs_lo, w_hi + W4_OFF, w_lo + W4_OFF, nullptr,
                                         nullptr, nullptr, gThi, gTlo, bst_base, tid);
    gemm<112, 64,  true , XS_PITCH, 112>(xs_hi, xs_lo, gThi, gTlo, b4,
                                         hs_hi, hs_lo, nullptr, nullptr, bst_base, tid);

    __syncthreads();
    // Layer 5 (project-first): g5[m] = sum_k h[m][k] * W5[k]
    if (tid < NODE) {
        float acc = 0.f;
        #pragma unroll
        for (int k = 0; k < 64; k++) {
            float hv = __bfloat162float(hs_hi[tid * HS_PITCH + k])
                     + __bfloat162float(hs_lo[tid * HS_PITCH + k]);
            acc += hv * __ldg(&W5[k]);
        }
        g5[tid] = acc;
    }
    __syncthreads();
    if (tid < NODE) {
        float acc = 0.f;
        #pragma unroll
        for (int j = 0; j < NODE; j++) {
            float xv = __bfloat162float(xs_hi[tid * XS_PITCH + j])
                     + __bfloat162float(xs_lo[tid * XS_PITCH + j]);
            acc += xv * g5[j];
        }
        float h5 = fmaxf(acc + __ldg(&b5[0]), 0.f);
        red[tid] = h5 * __ldg(&Wf[tid]);
    }
    __syncthreads();
    if (tid == 0) {
        float s = 0.f;
        #pragma unroll
        for (int i = 0; i < NODE; i++) s += red[i];
        out[b] = s + __ldg(&bf[0]);
    }
}

extern "C" void kernel_launch(void* const* d_in, const int* in_sizes, int n_in,
                              void* d_out, int out_size) {
    const float* x  = (const float*)d_in[0];
    const float* W1 = (const float*)d_in[1];
    const float* b1 = (const float*)d_in[2];
    const float* W2 = (const float*)d_in[3];
    const float* b2 = (const float*)d_in[4];
    const float* W3 = (const float*)d_in[5];
    const float* b3 = (const float*)d_in[6];
    const float* W4 = (const float*)d_in[7];
    const float* b4 = (const float*)d_in[8];
    const float* W5 = (const float*)d_in[9];
    const float* b5 = (const float*)d_in[10];
    const float* Wf = (const float*)d_in[11];
    const float* bf = (const float*)d_in[12];
    float* out = (float*)d_out;

    prep_weights<<<(W_TOTAL + 255) / 256, 256>>>(W1, W2, W3, W4);

    cudaFuncSetAttribute(gcn_fused_kernel,
                         cudaFuncAttributeMaxDynamicSharedMemorySize, SMEM_BYTES);
    gcn_fused_kernel<<<4096, 512, SMEM_BYTES>>>(
        x, b1, b2, b3, b4, W5, b5, Wf, bf, out);
}